// round 16
// baseline (speedup 1.0000x reference)
#include <cuda_runtime.h>
#include <cuda_bf16.h>
#include <cstdint>

// Problem constants
#define Nn  8192
#define FIN 512
#define HH  256
#define LL  64
#define EE  262144

typedef __nv_bfloat16 bf16;

// Scratch (device globals; no allocation allowed)
__device__ int   g_cnt[Nn];
__device__ int   g_off[Nn + 1];
__device__ int   g_cur[Nn];
__device__ int   g_csr_src[EE];
__device__ float g_csr_w[EE];
__device__ float g_dinv[Nn];
__device__ float g_xw1[Nn * HH];     // x @ W1 (fp32)
__device__ float g_uv[Nn * 128];     // [h@Wmu | h@Wsig]
__device__ bf16  g_za[Nn * 192];     // [hi | hi | lo]
__device__ bf16  g_zb[Nn * 192];     // [hi | lo | hi]
// bf16 split operands
__device__ bf16 g_xhi[Nn * FIN];
__device__ bf16 g_xlo[Nn * FIN];
__device__ bf16 g_w1thi[HH * FIN];   // W1^T [256][512]
__device__ bf16 g_w1tlo[HH * FIN];
__device__ bf16 g_hhi[Nn * HH];
__device__ bf16 g_hlo[Nn * HH];
__device__ bf16 g_whthi[128 * HH];   // [Wmu|Wsig]^T [128][256]
__device__ bf16 g_whtlo[128 * HH];

__device__ __forceinline__ float sigf(float x) {
    return 1.0f / (1.0f + __expf(-x));
}

// ---------------- CSR build ----------------
__global__ void k_zero_cnt() {
    int i = blockIdx.x * blockDim.x + threadIdx.x;
    if (i < Nn) g_cnt[i] = 0;
}
__global__ void k_deg_i(const int* __restrict__ ei) {
    int e = blockIdx.x * blockDim.x + threadIdx.x;
    if (e < EE) atomicAdd(&g_cnt[ei[EE + e]], 1);
}
__global__ void k_scan() {
    __shared__ int ssum[256];
    int t = threadIdx.x;
    int base = t * 32;
    int s = 0;
#pragma unroll
    for (int i = 0; i < 32; i++) s += g_cnt[base + i];
    ssum[t] = s;
    __syncthreads();
    if (t == 0) {
        int run = 0;
        for (int i = 0; i < 256; i++) { int v = ssum[i]; ssum[i] = run; run += v; }
        g_off[Nn] = run;
    }
    __syncthreads();
    int run = ssum[t];
#pragma unroll
    for (int i = 0; i < 32; i++) {
        int c = g_cnt[base + i];
        g_off[base + i] = run;
        g_cur[base + i] = run;
        g_dinv[base + i] = rsqrtf((float)c + 1.0f);
        run += c;
    }
}
__global__ void k_fill(const int* __restrict__ ei) {
    int e = blockIdx.x * blockDim.x + threadIdx.x;
    if (e < EE) {
        int src = ei[e], dst = ei[EE + e];
        int pos = atomicAdd(&g_cur[dst], 1);
        g_csr_src[pos] = src;
        g_csr_w[pos] = g_dinv[src] * g_dinv[dst];
    }
}

// ---------------- bf16 hi/lo splits ----------------
__device__ __forceinline__ void split_store(bf16* hi, bf16* lo, int i4, float4 v) {
    bf16 h0 = __float2bfloat16_rn(v.x), h1 = __float2bfloat16_rn(v.y);
    bf16 h2 = __float2bfloat16_rn(v.z), h3 = __float2bfloat16_rn(v.w);
    bf16 l0 = __float2bfloat16_rn(v.x - __bfloat162float(h0));
    bf16 l1 = __float2bfloat16_rn(v.y - __bfloat162float(h1));
    bf16 l2 = __float2bfloat16_rn(v.z - __bfloat162float(h2));
    bf16 l3 = __float2bfloat16_rn(v.w - __bfloat162float(h3));
    __nv_bfloat162* hp = (__nv_bfloat162*)(hi + (size_t)i4 * 4);
    __nv_bfloat162* lp = (__nv_bfloat162*)(lo + (size_t)i4 * 4);
    hp[0] = __nv_bfloat162(h0, h1);
    hp[1] = __nv_bfloat162(h2, h3);
    lp[0] = __nv_bfloat162(l0, l1);
    lp[1] = __nv_bfloat162(l2, l3);
}

__global__ void k_split_x(const float* __restrict__ x) {
    int i = blockIdx.x * blockDim.x + threadIdx.x;
    if (i < Nn * FIN / 4) split_store(g_xhi, g_xlo, i, *((const float4*)x + i));
}

// combined weight transpose+split: W1 and [Wmu|Wsig]
__global__ void k_split_w(const float* __restrict__ W1,
                          const float* __restrict__ Wmu,
                          const float* __restrict__ Wsig) {
    int t = blockIdx.x * blockDim.x + threadIdx.x;
    if (t < FIN * HH) {
        int k = t / HH, n = t % HH;
        float v = W1[t];
        bf16 h = __float2bfloat16_rn(v);
        bf16 l = __float2bfloat16_rn(v - __bfloat162float(h));
        g_w1thi[(size_t)n * FIN + k] = h;
        g_w1tlo[(size_t)n * FIN + k] = l;
    } else if (t < FIN * HH + HH * 128) {
        int u = t - FIN * HH;
        int k = u / 128, n = u % 128;
        float v = (n < 64) ? Wmu[(size_t)k * 64 + n] : Wsig[(size_t)k * 64 + (n - 64)];
        bf16 h = __float2bfloat16_rn(v);
        bf16 l = __float2bfloat16_rn(v - __bfloat162float(h));
        g_whthi[(size_t)n * HH + k] = h;
        g_whtlo[(size_t)n * HH + k] = l;
    }
}

// ---------------- mma helpers ----------------
__device__ __forceinline__ void mma16816(float* d, uint32_t a0, uint32_t a1,
                                         uint32_t a2, uint32_t a3,
                                         uint32_t b0, uint32_t b1) {
    asm volatile(
        "mma.sync.aligned.m16n8k16.row.col.f32.bf16.bf16.f32 "
        "{%0,%1,%2,%3}, {%4,%5,%6,%7}, {%8,%9}, {%0,%1,%2,%3};"
        : "+f"(d[0]), "+f"(d[1]), "+f"(d[2]), "+f"(d[3])
        : "r"(a0), "r"(a1), "r"(a2), "r"(a3), "r"(b0), "r"(b1));
}
__device__ __forceinline__ void ldmx4(uint32_t& r0, uint32_t& r1, uint32_t& r2,
                                      uint32_t& r3, uint32_t addr) {
    asm volatile("ldmatrix.sync.aligned.m8n8.x4.shared.b16 {%0,%1,%2,%3}, [%4];"
                 : "=r"(r0), "=r"(r1), "=r"(r2), "=r"(r3) : "r"(addr));
}
__device__ __forceinline__ void cpasync16(uint32_t dst, const void* src) {
    asm volatile("cp.async.cg.shared.global [%0], [%1], 16;"
                 :: "r"(dst), "l"(src) : "memory");
}

#define KT   128
#define TPW  68

// ------- gemm1: 512 threads, tile 128x256 (full N), grid (1,64) -------
// 16 warps (4 wm x 4 wn) -> 4 warps/SMSP hides ldsm->mma latency;
// A tile loaded once per block (was twice with 2 N-blocks).
__global__ __launch_bounds__(512) void k_gemm1_big() {
    constexpr int K = FIN;
    extern __shared__ uint32_t smw[];
    uint32_t* sB = smw + 128 * TPW;
    int tid = threadIdx.x;
    int m0 = blockIdx.y * 128;

    int w = tid >> 5, lane = tid & 31;
    int wm = (w & 3) * 32;
    int wn = (w >> 2) * 64;
    int lr = lane & 15, lc = lane >> 4;
    uint32_t baseA = (uint32_t)__cvta_generic_to_shared(smw);
    uint32_t baseB = (uint32_t)__cvta_generic_to_shared(sB);

    float acc[2][8][4];
#pragma unroll
    for (int a = 0; a < 2; a++)
#pragma unroll
        for (int b = 0; b < 8; b++)
#pragma unroll
            for (int c = 0; c < 4; c++) acc[a][b][c] = 0.f;

    const bf16* pa[3] = {g_xhi, g_xhi, g_xlo};
    const bf16* pb[3] = {g_w1thi, g_w1tlo, g_w1thi};

    for (int ph = 0; ph < 3; ph++) {
        const bf16* A = pa[ph];
        const bf16* B = pb[ph];
        for (int kt = 0; kt < K; kt += KT) {
            for (int i = tid; i < 128 * 16; i += 512) {
                int r = i >> 4, q = i & 15;
                uint4 v = *(const uint4*)(A + (size_t)(m0 + r) * K + kt + q * 8);
                *(uint4*)(smw + r * TPW + q * 4) = v;
            }
            for (int i = tid; i < 256 * 16; i += 512) {
                int r = i >> 4, q = i & 15;
                uint4 v = *(const uint4*)(B + (size_t)r * K + kt + q * 8);
                *(uint4*)(sB + r * TPW + q * 4) = v;
            }
            __syncthreads();
#pragma unroll
            for (int ks = 0; ks < KT / 16; ks++) {
                uint32_t a0[2], a1[2], a2[2], a3[2];
#pragma unroll
                for (int mi = 0; mi < 2; mi++) {
                    uint32_t ad = baseA + (uint32_t)(wm + mi * 16 + lr) * (TPW * 4)
                                + ks * 32 + lc * 16;
                    ldmx4(a0[mi], a1[mi], a2[mi], a3[mi], ad);
                }
#pragma unroll
                for (int ni = 0; ni < 4; ni++) {
                    uint32_t b0, b1, b2, b3;
                    uint32_t bd = baseB + (uint32_t)(wn + ni * 16 + lr) * (TPW * 4)
                                + ks * 32 + lc * 16;
                    ldmx4(b0, b1, b2, b3, bd);
#pragma unroll
                    for (int mi = 0; mi < 2; mi++) {
                        mma16816(acc[mi][ni * 2 + 0], a0[mi], a1[mi], a2[mi], a3[mi], b0, b2);
                        mma16816(acc[mi][ni * 2 + 1], a0[mi], a1[mi], a2[mi], a3[mi], b1, b3);
                    }
                }
            }
            __syncthreads();
        }
    }

    int tr = lane >> 2, tc = (lane & 3) * 2;
#pragma unroll
    for (int mi = 0; mi < 2; mi++) {
#pragma unroll
        for (int half = 0; half < 2; half++) {
            int gr = m0 + wm + mi * 16 + tr + half * 8;
#pragma unroll
            for (int nj = 0; nj < 8; nj++) {
                int gc = wn + nj * 8 + tc;
                float2 o = {acc[mi][nj][half * 2 + 0], acc[mi][nj][half * 2 + 1]};
                *(float2*)(g_xw1 + (size_t)gr * 256 + gc) = o;
            }
        }
    }
}

// ------- gemm2 (MODE 1 of proven template): 256 threads, 64-row tiles -------
__global__ __launch_bounds__(256) void k_gemm2() {
    constexpr int K = HH;
    constexpr int MT = 64;
    extern __shared__ uint32_t smw[];
    uint32_t* sB = smw + MT * TPW;
    int tid = threadIdx.x;
    int m0 = blockIdx.y * MT;

    int w = tid >> 5, lane = tid & 31;
    int wm = (w & 3) * 16;
    int wn = (w >> 2) * 64;
    int lr = lane & 15, lc = lane >> 4;
    uint32_t baseA = (uint32_t)__cvta_generic_to_shared(smw);
    uint32_t baseB = (uint32_t)__cvta_generic_to_shared(sB);

    float acc[1][8][4];
#pragma unroll
    for (int b = 0; b < 8; b++)
#pragma unroll
        for (int c = 0; c < 4; c++) acc[0][b][c] = 0.f;

    const bf16* pa[3] = {g_hhi, g_hhi, g_hlo};
    const bf16* pb[3] = {g_whthi, g_whtlo, g_whthi};

    for (int ph = 0; ph < 3; ph++) {
        const bf16* A = pa[ph];
        const bf16* B = pb[ph];
        for (int kt = 0; kt < K; kt += KT) {
            for (int i = tid; i < MT * 16; i += 256) {
                int r = i >> 4, q = i & 15;
                uint4 v = *(const uint4*)(A + (size_t)(m0 + r) * K + kt + q * 8);
                *(uint4*)(smw + r * TPW + q * 4) = v;
            }
            for (int i = tid; i < 128 * 16; i += 256) {
                int r = i >> 4, q = i & 15;
                uint4 v = *(const uint4*)(B + (size_t)r * K + kt + q * 8);
                *(uint4*)(sB + r * TPW + q * 4) = v;
            }
            __syncthreads();
#pragma unroll
            for (int ks = 0; ks < KT / 16; ks++) {
                uint32_t a0, a1, a2, a3;
                uint32_t ad = baseA + (uint32_t)(wm + lr) * (TPW * 4) + ks * 32 + lc * 16;
                ldmx4(a0, a1, a2, a3, ad);
#pragma unroll
                for (int ni = 0; ni < 4; ni++) {
                    uint32_t b0, b1, b2, b3;
                    uint32_t bd = baseB + (uint32_t)(wn + ni * 16 + lr) * (TPW * 4)
                                + ks * 32 + lc * 16;
                    ldmx4(b0, b1, b2, b3, bd);
                    mma16816(acc[0][ni * 2 + 0], a0, a1, a2, a3, b0, b2);
                    mma16816(acc[0][ni * 2 + 1], a0, a1, a2, a3, b1, b3);
                }
            }
            __syncthreads();
        }
    }

    int tr = lane >> 2, tc = (lane & 3) * 2;
#pragma unroll
    for (int half = 0; half < 2; half++) {
        int gr = m0 + wm + tr + half * 8;
#pragma unroll
        for (int nj = 0; nj < 8; nj++) {
            int gc = wn + nj * 8 + tc;
            float2 o = {acc[0][nj][half * 2 + 0], acc[0][nj][half * 2 + 1]};
            *(float2*)(g_uv + (size_t)gr * 128 + gc) = o;
        }
    }
}

// ------- gather layer 1 -------
__global__ __launch_bounds__(64) void k_gather1(const float* __restrict__ b1) {
    int n = blockIdx.x;
    int t = threadIdx.x;
    float dv = g_dinv[n];
    float d2 = dv * dv;
    float4 acc = *((const float4*)(g_xw1 + (size_t)n * HH) + t);
    acc.x *= d2; acc.y *= d2; acc.z *= d2; acc.w *= d2;
    int e0 = g_off[n], e1 = g_off[n + 1];
    for (int e = e0; e < e1; e++) {
        int src = g_csr_src[e];
        float wgt = g_csr_w[e];
        float4 u = *((const float4*)(g_xw1 + (size_t)src * HH) + t);
        acc.x += u.x * wgt; acc.y += u.y * wgt; acc.z += u.z * wgt; acc.w += u.w * wgt;
    }
    float4 b = ((const float4*)b1)[t];
    acc.x = fmaxf(acc.x + b.x, 0.f);
    acc.y = fmaxf(acc.y + b.y, 0.f);
    acc.z = fmaxf(acc.z + b.z, 0.f);
    acc.w = fmaxf(acc.w + b.w, 0.f);
    split_store(g_hhi, g_hlo, n * 64 + t, acc);
}

// ------- gather layer 2 -------
__global__ __launch_bounds__(32) void k_gather2(const float* __restrict__ gn,
                                                const float* __restrict__ bmu,
                                                const float* __restrict__ bsig) {
    __shared__ float srow[128];
    int n = blockIdx.x;
    int t = threadIdx.x;
    float dv = g_dinv[n];
    float d2 = dv * dv;
    float4 acc = *((const float4*)(g_uv + (size_t)n * 128) + t);
    acc.x *= d2; acc.y *= d2; acc.z *= d2; acc.w *= d2;
    int e0 = g_off[n], e1 = g_off[n + 1];
    for (int e = e0; e < e1; e++) {
        int src = g_csr_src[e];
        float wgt = g_csr_w[e];
        float4 u = *((const float4*)(g_uv + (size_t)src * 128) + t);
        acc.x += u.x * wgt; acc.y += u.y * wgt; acc.z += u.z * wgt; acc.w += u.w * wgt;
    }
    *(float4*)(srow + 4 * t) = acc;
    __syncwarp();
    int l = 2 * t;
    float u0 = srow[l]     + bmu[l];
    float u1 = srow[l + 1] + bmu[l + 1];
    float s0 = srow[64 + l]     + bsig[l];
    float s1 = srow[64 + l + 1] + bsig[l + 1];
    float z0 = gn[(size_t)n * LL + l]     * expf(u0) + s0;
    float z1 = gn[(size_t)n * LL + l + 1] * expf(u1) + s1;
    bf16 h0 = __float2bfloat16_rn(z0);
    bf16 h1 = __float2bfloat16_rn(z1);
    bf16 l0 = __float2bfloat16_rn(z0 - __bfloat162float(h0));
    bf16 l1 = __float2bfloat16_rn(z1 - __bfloat162float(h1));
    __nv_bfloat162 hh(h0, h1), ll(l0, l1);
    size_t r = (size_t)n * 192;
    *(__nv_bfloat162*)(g_za + r + l)       = hh;
    *(__nv_bfloat162*)(g_za + r + 64 + l)  = hh;
    *(__nv_bfloat162*)(g_za + r + 128 + l) = ll;
    *(__nv_bfloat162*)(g_zb + r + l)       = hh;
    *(__nv_bfloat162*)(g_zb + r + 64 + l)  = ll;
    *(__nv_bfloat162*)(g_zb + r + 128 + l) = hh;
}

// ------- out = sigmoid(z z^T): triangular grid + cp.async 2-stage pipeline ---
#define ZPW     52
#define STG_W   (128 * ZPW)
#define STAGE_W (2 * STG_W)
#define OPITCH  129
#define NTRI    2080

__global__ __launch_bounds__(256, 2) void k_zzt_sym(float* __restrict__ out) {
    extern __shared__ uint32_t smw[];
    int t5 = blockIdx.x;
    int by = (int)(64.5f - sqrtf(64.5f * 64.5f - 2.0f * (float)t5));
    while (64 * (by + 1) - ((by + 1) * by) / 2 <= t5) by++;
    while (64 * by - (by * (by - 1)) / 2 > t5) by--;
    int bx = by + (t5 - (64 * by - (by * (by - 1)) / 2));
    int m0 = by * 128, n0 = bx * 128;

    int tid = threadIdx.x;
    uint32_t sbase = (uint32_t)__cvta_generic_to_shared(smw);

#pragma unroll
    for (int st = 0; st < 2; st++) {
        uint32_t dA = sbase + st * (STAGE_W * 4);
        uint32_t dB = dA + STG_W * 4;
        for (int i = tid; i < 128 * 12; i += 256) {
            int r = i / 12, q = i % 12;
            cpasync16(dA + r * 208 + q * 16,
                      g_za + (size_t)(m0 + r) * 192 + st * 96 + q * 8);
            cpasync16(dB + r * 208 + q * 16,
                      g_zb + (size_t)(n0 + r) * 192 + st * 96 + q * 8);
        }
        asm volatile("cp.async.commit_group;" ::: "memory");
    }

    int w = tid >> 5, lane = tid & 31;
    int wm = (w & 3) * 32;
    int wn = (w >> 2) * 64;
    int lr = lane & 15, lc = lane >> 4;

    float acc[2][8][4];
#pragma unroll
    for (int a = 0; a < 2; a++)
#pragma unroll
        for (int b = 0; b < 8; b++)
#pragma unroll
            for (int c = 0; c < 4; c++) acc[a][b][c] = 0.f;

#pragma unroll
    for (int st = 0; st < 2; st++) {
        if (st == 0) {
            asm volatile("cp.async.wait_group 1;" ::: "memory");
        } else {
            asm volatile("cp.async.wait_group 0;" ::: "memory");
        }
        __syncthreads();
        uint32_t baseA = sbase + st * (STAGE_W * 4);
        uint32_t baseB = baseA + STG_W * 4;
#pragma unroll
        for (int ks = 0; ks < 6; ks++) {
            uint32_t a0[2], a1[2], a2[2], a3[2];
#pragma unroll
            for (int mi = 0; mi < 2; mi++) {
                uint32_t ad = baseA + (uint32_t)(wm + mi * 16 + lr) * 208 + ks * 32 + lc * 16;
                ldmx4(a0[mi], a1[mi], a2[mi], a3[mi], ad);
            }
#pragma unroll
            for (int ni = 0; ni < 4; ni++) {
                uint32_t b0, b1, b2, b3;
                uint32_t bd = baseB + (uint32_t)(wn + ni * 16 + lr) * 208 + ks * 32 + lc * 16;
                ldmx4(b0, b1, b2, b3, bd);
#pragma unroll
                for (int mi = 0; mi < 2; mi++) {
                    mma16816(acc[mi][ni * 2 + 0], a0[mi], a1[mi], a2[mi], a3[mi], b0, b2);
                    mma16816(acc[mi][ni * 2 + 1], a0[mi], a1[mi], a2[mi], a3[mi], b1, b3);
                }
            }
        }
    }

    __syncthreads();
    float* sO = (float*)smw;
    int tr = lane >> 2, tc = (lane & 3) * 2;
#pragma unroll
    for (int mi = 0; mi < 2; mi++) {
#pragma unroll
        for (int nj = 0; nj < 8; nj++) {
            int rr0 = wm + mi * 16 + tr;
            int cc = wn + nj * 8 + tc;
            sO[rr0 * OPITCH + cc]           = sigf(acc[mi][nj][0]);
            sO[rr0 * OPITCH + cc + 1]       = sigf(acc[mi][nj][1]);
            sO[(rr0 + 8) * OPITCH + cc]     = sigf(acc[mi][nj][2]);
            sO[(rr0 + 8) * OPITCH + cc + 1] = sigf(acc[mi][nj][3]);
        }
    }
    __syncthreads();

    for (int i = tid; i < 128 * 32; i += 256) {
        int r = i >> 5, c = (i & 31) * 4;
        float4 v = {sO[r * OPITCH + c], sO[r * OPITCH + c + 1],
                    sO[r * OPITCH + c + 2], sO[r * OPITCH + c + 3]};
        *(float4*)(out + (size_t)(m0 + r) * Nn + n0 + c) = v;
    }
    if (bx != by) {
        for (int i = tid; i < 128 * 32; i += 256) {
            int r = i >> 5, c = (i & 31) * 4;
            float4 v = {sO[(c + 0) * OPITCH + r], sO[(c + 1) * OPITCH + r],
                        sO[(c + 2) * OPITCH + r], sO[(c + 3) * OPITCH + r]};
            *(float4*)(out + (size_t)(n0 + r) * Nn + m0 + c) = v;
        }
    }
}

// ---------------- launch (multi-stream: CSR build overlaps splits+gemm1) ----
extern "C" void kernel_launch(void* const* d_in, const int* in_sizes, int n_in,
                              void* d_out, int out_size) {
    const float* x    = (const float*)d_in[0];
    const int*   ei   = (const int*)d_in[1];
    const float* W1   = (const float*)d_in[2];
    const float* b1   = (const float*)d_in[3];
    const float* Wmu  = (const float*)d_in[4];
    const float* bmu  = (const float*)d_in[5];
    const float* Wsig = (const float*)d_in[6];
    const float* bsig = (const float*)d_in[7];
    const float* gn   = (const float*)d_in[8];
    float* out = (float*)d_out;
    (void)in_sizes; (void)n_in; (void)out_size;

    static cudaStream_t s2 = []() {
        cudaStream_t s; cudaStreamCreateWithFlags(&s, cudaStreamNonBlocking); return s;
    }();
    static cudaEvent_t evF = []() {
        cudaEvent_t e; cudaEventCreateWithFlags(&e, cudaEventDisableTiming); return e;
    }();
    static cudaEvent_t evJ = []() {
        cudaEvent_t e; cudaEventCreateWithFlags(&e, cudaEventDisableTiming); return e;
    }();

    int smem_g1 = (128 + 256) * TPW * 4;   // 104448
    int smem_g2 = (64 + 128) * TPW * 4;    // 52224
    int smem_zz = 2 * STAGE_W * 4;         // 106496
    cudaFuncSetAttribute(k_gemm1_big, cudaFuncAttributeMaxDynamicSharedMemorySize, smem_g1);
    cudaFuncSetAttribute(k_gemm2, cudaFuncAttributeMaxDynamicSharedMemorySize, smem_g2);
    cudaFuncSetAttribute(k_zzt_sym, cudaFuncAttributeMaxDynamicSharedMemorySize, smem_zz);

    // fork: side stream runs the CSR build chain
    cudaEventRecord(evF, 0);
    cudaStreamWaitEvent(s2, evF, 0);
    k_zero_cnt<<<Nn / 256, 256, 0, s2>>>();
    k_deg_i<<<EE / 256, 256, 0, s2>>>(ei);
    k_scan<<<1, 256, 0, s2>>>();
    k_fill<<<EE / 256, 256, 0, s2>>>(ei);
    cudaEventRecord(evJ, s2);

    // main stream: splits + layer-1 GEMM (independent of CSR build)
    k_split_x<<<(Nn * FIN / 4 + 255) / 256, 256>>>(x);
    k_split_w<<<(FIN * HH + HH * 128 + 255) / 256, 256>>>(W1, Wmu, Wsig);
    k_gemm1_big<<<dim3(1, 64), 512, smem_g1>>>();

    // join: gather needs CSR + dinv + gemm1 output
    cudaStreamWaitEvent(0, evJ, 0);
    k_gather1<<<Nn, 64>>>(b1);

    // layer 2
    k_gemm2<<<dim3(1, 128), 256, smem_g2>>>();
    k_gather2<<<Nn, 32>>>(gn, bmu, bsig);

    k_zzt_sym<<<NTRI, 256, smem_zz>>>(out);
}

// round 17
// speedup vs baseline: 1.1212x; 1.1212x over previous
#include <cuda_runtime.h>
#include <cuda_bf16.h>
#include <cstdint>

// Problem constants
#define Nn  8192
#define FIN 512
#define HH  256
#define LL  64
#define EE  262144

typedef __nv_bfloat16 bf16;

// Scratch (device globals; no allocation allowed)
__device__ int   g_cnt[Nn];
__device__ int   g_off[Nn + 1];
__device__ int   g_cur[Nn];
__device__ int   g_csr_src[EE];
__device__ float g_csr_w[EE];
__device__ float g_dinv[Nn];
__device__ float g_xw1[Nn * HH];     // x @ W1 (fp32)
__device__ float g_uv[Nn * 128];     // [h@Wmu | h@Wsig]
__device__ bf16  g_za[Nn * 192];     // [hi | hi | lo]
__device__ bf16  g_zb[Nn * 192];     // [hi | lo | hi]
// bf16 split operands
__device__ bf16 g_xhi[Nn * FIN];
__device__ bf16 g_xlo[Nn * FIN];
__device__ bf16 g_w1thi[HH * FIN];   // W1^T [256][512]
__device__ bf16 g_w1tlo[HH * FIN];
__device__ bf16 g_hhi[Nn * HH];
__device__ bf16 g_hlo[Nn * HH];
__device__ bf16 g_whthi[128 * HH];   // [Wmu|Wsig]^T [128][256]
__device__ bf16 g_whtlo[128 * HH];

__device__ __forceinline__ float sigf(float x) {
    return 1.0f / (1.0f + __expf(-x));
}

// ---------------- CSR build ----------------
__global__ void k_zero_cnt() {
    int i = blockIdx.x * blockDim.x + threadIdx.x;
    if (i < Nn) g_cnt[i] = 0;
}
__global__ void k_deg_i(const int* __restrict__ ei) {
    int e = blockIdx.x * blockDim.x + threadIdx.x;
    if (e < EE) atomicAdd(&g_cnt[ei[EE + e]], 1);
}
__global__ void k_scan() {
    __shared__ int ssum[256];
    int t = threadIdx.x;
    int base = t * 32;
    int s = 0;
#pragma unroll
    for (int i = 0; i < 32; i++) s += g_cnt[base + i];
    ssum[t] = s;
    __syncthreads();
    if (t == 0) {
        int run = 0;
        for (int i = 0; i < 256; i++) { int v = ssum[i]; ssum[i] = run; run += v; }
        g_off[Nn] = run;
    }
    __syncthreads();
    int run = ssum[t];
#pragma unroll
    for (int i = 0; i < 32; i++) {
        int c = g_cnt[base + i];
        g_off[base + i] = run;
        g_cur[base + i] = run;
        g_dinv[base + i] = rsqrtf((float)c + 1.0f);
        run += c;
    }
}
__global__ void k_fill(const int* __restrict__ ei) {
    int e = blockIdx.x * blockDim.x + threadIdx.x;
    if (e < EE) {
        int src = ei[e], dst = ei[EE + e];
        int pos = atomicAdd(&g_cur[dst], 1);
        g_csr_src[pos] = src;
        g_csr_w[pos] = g_dinv[src] * g_dinv[dst];
    }
}

// ---------------- bf16 hi/lo splits ----------------
__device__ __forceinline__ void split_store(bf16* hi, bf16* lo, int i4, float4 v) {
    bf16 h0 = __float2bfloat16_rn(v.x), h1 = __float2bfloat16_rn(v.y);
    bf16 h2 = __float2bfloat16_rn(v.z), h3 = __float2bfloat16_rn(v.w);
    bf16 l0 = __float2bfloat16_rn(v.x - __bfloat162float(h0));
    bf16 l1 = __float2bfloat16_rn(v.y - __bfloat162float(h1));
    bf16 l2 = __float2bfloat16_rn(v.z - __bfloat162float(h2));
    bf16 l3 = __float2bfloat16_rn(v.w - __bfloat162float(h3));
    __nv_bfloat162* hp = (__nv_bfloat162*)(hi + (size_t)i4 * 4);
    __nv_bfloat162* lp = (__nv_bfloat162*)(lo + (size_t)i4 * 4);
    hp[0] = __nv_bfloat162(h0, h1);
    hp[1] = __nv_bfloat162(h2, h3);
    lp[0] = __nv_bfloat162(l0, l1);
    lp[1] = __nv_bfloat162(l2, l3);
}

__global__ void k_split_x(const float* __restrict__ x) {
    int i = blockIdx.x * blockDim.x + threadIdx.x;
    if (i < Nn * FIN / 4) split_store(g_xhi, g_xlo, i, *((const float4*)x + i));
}

// combined weight transpose+split: W1 and [Wmu|Wsig]
__global__ void k_split_w(const float* __restrict__ W1,
                          const float* __restrict__ Wmu,
                          const float* __restrict__ Wsig) {
    int t = blockIdx.x * blockDim.x + threadIdx.x;
    if (t < FIN * HH) {
        int k = t / HH, n = t % HH;
        float v = W1[t];
        bf16 h = __float2bfloat16_rn(v);
        bf16 l = __float2bfloat16_rn(v - __bfloat162float(h));
        g_w1thi[(size_t)n * FIN + k] = h;
        g_w1tlo[(size_t)n * FIN + k] = l;
    } else if (t < FIN * HH + HH * 128) {
        int u = t - FIN * HH;
        int k = u / 128, n = u % 128;
        float v = (n < 64) ? Wmu[(size_t)k * 64 + n] : Wsig[(size_t)k * 64 + (n - 64)];
        bf16 h = __float2bfloat16_rn(v);
        bf16 l = __float2bfloat16_rn(v - __bfloat162float(h));
        g_whthi[(size_t)n * HH + k] = h;
        g_whtlo[(size_t)n * HH + k] = l;
    }
}

// ---------------- mma helpers ----------------
__device__ __forceinline__ void mma16816(float* d, uint32_t a0, uint32_t a1,
                                         uint32_t a2, uint32_t a3,
                                         uint32_t b0, uint32_t b1) {
    asm volatile(
        "mma.sync.aligned.m16n8k16.row.col.f32.bf16.bf16.f32 "
        "{%0,%1,%2,%3}, {%4,%5,%6,%7}, {%8,%9}, {%0,%1,%2,%3};"
        : "+f"(d[0]), "+f"(d[1]), "+f"(d[2]), "+f"(d[3])
        : "r"(a0), "r"(a1), "r"(a2), "r"(a3), "r"(b0), "r"(b1));
}
__device__ __forceinline__ void ldmx4(uint32_t& r0, uint32_t& r1, uint32_t& r2,
                                      uint32_t& r3, uint32_t addr) {
    asm volatile("ldmatrix.sync.aligned.m8n8.x4.shared.b16 {%0,%1,%2,%3}, [%4];"
                 : "=r"(r0), "=r"(r1), "=r"(r2), "=r"(r3) : "r"(addr));
}
__device__ __forceinline__ void cpasync16(uint32_t dst, const void* src) {
    asm volatile("cp.async.cg.shared.global [%0], [%1], 16;"
                 :: "r"(dst), "l"(src) : "memory");
}

#define KT   128
#define TPW  68

// ------- gemm1: fused 3-phase over shared K-tile (Ahi,Alo,Bhi,Blo resident) --
// grid (2,64), 256 threads, tile 128x128; per kt: load 4 tiles once, run
// (hi,hi),(hi,lo),(lo,hi) mma passes -> 1/3 fewer loads + 1/3 the syncs.
__global__ __launch_bounds__(256) void k_gemm1_f() {
    constexpr int K = FIN;
    extern __shared__ uint32_t smw[];
    int tid = threadIdx.x;
    int m0 = blockIdx.y * 128, n0 = blockIdx.x * 128;

    int w = tid >> 5, lane = tid & 31;
    int wm = (w & 3) * 32;
    int wn = (w >> 2) * 64;
    int lr = lane & 15, lc = lane >> 4;
    uint32_t sbase = (uint32_t)__cvta_generic_to_shared(smw);
    // tile bases (words): Ahi 0, Alo 128*TPW, Bhi 256*TPW, Blo 384*TPW
    const uint32_t oAhi = 0, oAlo = 128 * TPW * 4;
    const uint32_t oBhi = 256 * TPW * 4, oBlo = 384 * TPW * 4;

    float acc[2][8][4];
#pragma unroll
    for (int a = 0; a < 2; a++)
#pragma unroll
        for (int b = 0; b < 8; b++)
#pragma unroll
            for (int c = 0; c < 4; c++) acc[a][b][c] = 0.f;

    for (int kt = 0; kt < K; kt += KT) {
        // load 4 tiles (each 128 rows x 16 uint4)
        for (int i = tid; i < 128 * 16; i += 256) {
            int r = i >> 4, q = i & 15;
            uint32_t so = (uint32_t)(r * TPW + q * 4) * 4;
            size_t ga = (size_t)(m0 + r) * K + kt + q * 8;
            size_t gb = (size_t)(n0 + r) * K + kt + q * 8;
            *(uint4*)((char*)smw + oAhi + so) = *(const uint4*)(g_xhi + ga);
            *(uint4*)((char*)smw + oAlo + so) = *(const uint4*)(g_xlo + ga);
            *(uint4*)((char*)smw + oBhi + so) = *(const uint4*)(g_w1thi + gb);
            *(uint4*)((char*)smw + oBlo + so) = *(const uint4*)(g_w1tlo + gb);
        }
        __syncthreads();

        const uint32_t phA[3] = {oAhi, oAhi, oAlo};
        const uint32_t phB[3] = {oBhi, oBlo, oBhi};
#pragma unroll
        for (int ph = 0; ph < 3; ph++) {
            uint32_t baseA = sbase + phA[ph];
            uint32_t baseB = sbase + phB[ph];
#pragma unroll
            for (int ks = 0; ks < KT / 16; ks++) {
                uint32_t a0[2], a1[2], a2[2], a3[2];
#pragma unroll
                for (int mi = 0; mi < 2; mi++) {
                    uint32_t ad = baseA + (uint32_t)(wm + mi * 16 + lr) * (TPW * 4)
                                + ks * 32 + lc * 16;
                    ldmx4(a0[mi], a1[mi], a2[mi], a3[mi], ad);
                }
#pragma unroll
                for (int ni = 0; ni < 4; ni++) {
                    uint32_t b0, b1, b2, b3;
                    uint32_t bd = baseB + (uint32_t)(wn + ni * 16 + lr) * (TPW * 4)
                                + ks * 32 + lc * 16;
                    ldmx4(b0, b1, b2, b3, bd);
#pragma unroll
                    for (int mi = 0; mi < 2; mi++) {
                        mma16816(acc[mi][ni * 2 + 0], a0[mi], a1[mi], a2[mi], a3[mi], b0, b2);
                        mma16816(acc[mi][ni * 2 + 1], a0[mi], a1[mi], a2[mi], a3[mi], b1, b3);
                    }
                }
            }
        }
        __syncthreads();
    }

    int tr = lane >> 2, tc = (lane & 3) * 2;
#pragma unroll
    for (int mi = 0; mi < 2; mi++) {
#pragma unroll
        for (int half = 0; half < 2; half++) {
            int gr = m0 + wm + mi * 16 + tr + half * 8;
#pragma unroll
            for (int nj = 0; nj < 8; nj++) {
                int gc = n0 + wn + nj * 8 + tc;
                float2 o = {acc[mi][nj][half * 2 + 0], acc[mi][nj][half * 2 + 1]};
                *(float2*)(g_xw1 + (size_t)gr * 256 + gc) = o;
            }
        }
    }
}

// ------- gemm2 (R15-proven MODE 1): 256 threads, 64-row tiles, grid (1,128) --
__global__ __launch_bounds__(256) void k_gemm2() {
    constexpr int K = HH;
    constexpr int MT = 64;
    extern __shared__ uint32_t smw[];
    uint32_t* sB = smw + MT * TPW;
    int tid = threadIdx.x;
    int m0 = blockIdx.y * MT;

    int w = tid >> 5, lane = tid & 31;
    int wm = (w & 3) * 16;
    int wn = (w >> 2) * 64;
    int lr = lane & 15, lc = lane >> 4;
    uint32_t baseA = (uint32_t)__cvta_generic_to_shared(smw);
    uint32_t baseB = (uint32_t)__cvta_generic_to_shared(sB);

    float acc[1][8][4];
#pragma unroll
    for (int b = 0; b < 8; b++)
#pragma unroll
        for (int c = 0; c < 4; c++) acc[0][b][c] = 0.f;

    const bf16* pa[3] = {g_hhi, g_hhi, g_hlo};
    const bf16* pb[3] = {g_whthi, g_whtlo, g_whthi};

    for (int ph = 0; ph < 3; ph++) {
        const bf16* A = pa[ph];
        const bf16* B = pb[ph];
        for (int kt = 0; kt < K; kt += KT) {
            for (int i = tid; i < MT * 16; i += 256) {
                int r = i >> 4, q = i & 15;
                uint4 v = *(const uint4*)(A + (size_t)(m0 + r) * K + kt + q * 8);
                *(uint4*)(smw + r * TPW + q * 4) = v;
            }
            for (int i = tid; i < 128 * 16; i += 256) {
                int r = i >> 4, q = i & 15;
                uint4 v = *(const uint4*)(B + (size_t)r * K + kt + q * 8);
                *(uint4*)(sB + r * TPW + q * 4) = v;
            }
            __syncthreads();
#pragma unroll
            for (int ks = 0; ks < KT / 16; ks++) {
                uint32_t a0, a1, a2, a3;
                uint32_t ad = baseA + (uint32_t)(wm + lr) * (TPW * 4) + ks * 32 + lc * 16;
                ldmx4(a0, a1, a2, a3, ad);
#pragma unroll
                for (int ni = 0; ni < 4; ni++) {
                    uint32_t b0, b1, b2, b3;
                    uint32_t bd = baseB + (uint32_t)(wn + ni * 16 + lr) * (TPW * 4)
                                + ks * 32 + lc * 16;
                    ldmx4(b0, b1, b2, b3, bd);
                    mma16816(acc[0][ni * 2 + 0], a0, a1, a2, a3, b0, b2);
                    mma16816(acc[0][ni * 2 + 1], a0, a1, a2, a3, b1, b3);
                }
            }
            __syncthreads();
        }
    }

    int tr = lane >> 2, tc = (lane & 3) * 2;
#pragma unroll
    for (int half = 0; half < 2; half++) {
        int gr = m0 + wm + tr + half * 8;
#pragma unroll
        for (int nj = 0; nj < 8; nj++) {
            int gc = wn + nj * 8 + tc;
            float2 o = {acc[0][nj][half * 2 + 0], acc[0][nj][half * 2 + 1]};
            *(float2*)(g_uv + (size_t)gr * 128 + gc) = o;
        }
    }
}

// ------- gather layer 1 -------
__global__ __launch_bounds__(64) void k_gather1(const float* __restrict__ b1) {
    int n = blockIdx.x;
    int t = threadIdx.x;
    float dv = g_dinv[n];
    float d2 = dv * dv;
    float4 acc = *((const float4*)(g_xw1 + (size_t)n * HH) + t);
    acc.x *= d2; acc.y *= d2; acc.z *= d2; acc.w *= d2;
    int e0 = g_off[n], e1 = g_off[n + 1];
    for (int e = e0; e < e1; e++) {
        int src = g_csr_src[e];
        float wgt = g_csr_w[e];
        float4 u = *((const float4*)(g_xw1 + (size_t)src * HH) + t);
        acc.x += u.x * wgt; acc.y += u.y * wgt; acc.z += u.z * wgt; acc.w += u.w * wgt;
    }
    float4 b = ((const float4*)b1)[t];
    acc.x = fmaxf(acc.x + b.x, 0.f);
    acc.y = fmaxf(acc.y + b.y, 0.f);
    acc.z = fmaxf(acc.z + b.z, 0.f);
    acc.w = fmaxf(acc.w + b.w, 0.f);
    split_store(g_hhi, g_hlo, n * 64 + t, acc);
}

// ------- gather layer 2 -------
__global__ __launch_bounds__(32) void k_gather2(const float* __restrict__ gn,
                                                const float* __restrict__ bmu,
                                                const float* __restrict__ bsig) {
    __shared__ float srow[128];
    int n = blockIdx.x;
    int t = threadIdx.x;
    float dv = g_dinv[n];
    float d2 = dv * dv;
    float4 acc = *((const float4*)(g_uv + (size_t)n * 128) + t);
    acc.x *= d2; acc.y *= d2; acc.z *= d2; acc.w *= d2;
    int e0 = g_off[n], e1 = g_off[n + 1];
    for (int e = e0; e < e1; e++) {
        int src = g_csr_src[e];
        float wgt = g_csr_w[e];
        float4 u = *((const float4*)(g_uv + (size_t)src * 128) + t);
        acc.x += u.x * wgt; acc.y += u.y * wgt; acc.z += u.z * wgt; acc.w += u.w * wgt;
    }
    *(float4*)(srow + 4 * t) = acc;
    __syncwarp();
    int l = 2 * t;
    float u0 = srow[l]     + bmu[l];
    float u1 = srow[l + 1] + bmu[l + 1];
    float s0 = srow[64 + l]     + bsig[l];
    float s1 = srow[64 + l + 1] + bsig[l + 1];
    float z0 = gn[(size_t)n * LL + l]     * expf(u0) + s0;
    float z1 = gn[(size_t)n * LL + l + 1] * expf(u1) + s1;
    bf16 h0 = __float2bfloat16_rn(z0);
    bf16 h1 = __float2bfloat16_rn(z1);
    bf16 l0 = __float2bfloat16_rn(z0 - __bfloat162float(h0));
    bf16 l1 = __float2bfloat16_rn(z1 - __bfloat162float(h1));
    __nv_bfloat162 hh(h0, h1), ll(l0, l1);
    size_t r = (size_t)n * 192;
    *(__nv_bfloat162*)(g_za + r + l)       = hh;
    *(__nv_bfloat162*)(g_za + r + 64 + l)  = hh;
    *(__nv_bfloat162*)(g_za + r + 128 + l) = ll;
    *(__nv_bfloat162*)(g_zb + r + l)       = hh;
    *(__nv_bfloat162*)(g_zb + r + 64 + l)  = ll;
    *(__nv_bfloat162*)(g_zb + r + 128 + l) = hh;
}

// ------- out = sigmoid(z z^T): triangular grid + cp.async 2-stage pipeline ---
#define ZPW     52
#define STG_W   (128 * ZPW)
#define STAGE_W (2 * STG_W)
#define OPITCH  129
#define NTRI    2080

__global__ __launch_bounds__(256, 2) void k_zzt_sym(float* __restrict__ out) {
    extern __shared__ uint32_t smw[];
    int t5 = blockIdx.x;
    int by = (int)(64.5f - sqrtf(64.5f * 64.5f - 2.0f * (float)t5));
    while (64 * (by + 1) - ((by + 1) * by) / 2 <= t5) by++;
    while (64 * by - (by * (by - 1)) / 2 > t5) by--;
    int bx = by + (t5 - (64 * by - (by * (by - 1)) / 2));
    int m0 = by * 128, n0 = bx * 128;

    int tid = threadIdx.x;
    uint32_t sbase = (uint32_t)__cvta_generic_to_shared(smw);

#pragma unroll
    for (int st = 0; st < 2; st++) {
        uint32_t dA = sbase + st * (STAGE_W * 4);
        uint32_t dB = dA + STG_W * 4;
        for (int i = tid; i < 128 * 12; i += 256) {
            int r = i / 12, q = i % 12;
            cpasync16(dA + r * 208 + q * 16,
                      g_za + (size_t)(m0 + r) * 192 + st * 96 + q * 8);
            cpasync16(dB + r * 208 + q * 16,
                      g_zb + (size_t)(n0 + r) * 192 + st * 96 + q * 8);
        }
        asm volatile("cp.async.commit_group;" ::: "memory");
    }

    int w = tid >> 5, lane = tid & 31;
    int wm = (w & 3) * 32;
    int wn = (w >> 2) * 64;
    int lr = lane & 15, lc = lane >> 4;

    float acc[2][8][4];
#pragma unroll
    for (int a = 0; a < 2; a++)
#pragma unroll
        for (int b = 0; b < 8; b++)
#pragma unroll
            for (int c = 0; c < 4; c++) acc[a][b][c] = 0.f;

#pragma unroll
    for (int st = 0; st < 2; st++) {
        if (st == 0) {
            asm volatile("cp.async.wait_group 1;" ::: "memory");
        } else {
            asm volatile("cp.async.wait_group 0;" ::: "memory");
        }
        __syncthreads();
        uint32_t baseA = sbase + st * (STAGE_W * 4);
        uint32_t baseB = baseA + STG_W * 4;
#pragma unroll
        for (int ks = 0; ks < 6; ks++) {
            uint32_t a0[2], a1[2], a2[2], a3[2];
#pragma unroll
            for (int mi = 0; mi < 2; mi++) {
                uint32_t ad = baseA + (uint32_t)(wm + mi * 16 + lr) * 208 + ks * 32 + lc * 16;
                ldmx4(a0[mi], a1[mi], a2[mi], a3[mi], ad);
            }
#pragma unroll
            for (int ni = 0; ni < 4; ni++) {
                uint32_t b0, b1, b2, b3;
                uint32_t bd = baseB + (uint32_t)(wn + ni * 16 + lr) * 208 + ks * 32 + lc * 16;
                ldmx4(b0, b1, b2, b3, bd);
#pragma unroll
                for (int mi = 0; mi < 2; mi++) {
                    mma16816(acc[mi][ni * 2 + 0], a0[mi], a1[mi], a2[mi], a3[mi], b0, b2);
                    mma16816(acc[mi][ni * 2 + 1], a0[mi], a1[mi], a2[mi], a3[mi], b1, b3);
                }
            }
        }
    }

    __syncthreads();
    float* sO = (float*)smw;
    int tr = lane >> 2, tc = (lane & 3) * 2;
#pragma unroll
    for (int mi = 0; mi < 2; mi++) {
#pragma unroll
        for (int nj = 0; nj < 8; nj++) {
            int rr0 = wm + mi * 16 + tr;
            int cc = wn + nj * 8 + tc;
            sO[rr0 * OPITCH + cc]           = sigf(acc[mi][nj][0]);
            sO[rr0 * OPITCH + cc + 1]       = sigf(acc[mi][nj][1]);
            sO[(rr0 + 8) * OPITCH + cc]     = sigf(acc[mi][nj][2]);
            sO[(rr0 + 8) * OPITCH + cc + 1] = sigf(acc[mi][nj][3]);
        }
    }
    __syncthreads();

    for (int i = tid; i < 128 * 32; i += 256) {
        int r = i >> 5, c = (i & 31) * 4;
        float4 v = {sO[r * OPITCH + c], sO[r * OPITCH + c + 1],
                    sO[r * OPITCH + c + 2], sO[r * OPITCH + c + 3]};
        *(float4*)(out + (size_t)(m0 + r) * Nn + n0 + c) = v;
    }
    if (bx != by) {
        for (int i = tid; i < 128 * 32; i += 256) {
            int r = i >> 5, c = (i & 31) * 4;
            float4 v = {sO[(c + 0) * OPITCH + r], sO[(c + 1) * OPITCH + r],
                        sO[(c + 2) * OPITCH + r], sO[(c + 3) * OPITCH + r]};
            *(float4*)(out + (size_t)(n0 + r) * Nn + m0 + c) = v;
        }
    }
}

// ---------------- launch (multi-stream: CSR build overlaps splits+gemm1) ----
extern "C" void kernel_launch(void* const* d_in, const int* in_sizes, int n_in,
                              void* d_out, int out_size) {
    const float* x    = (const float*)d_in[0];
    const int*   ei   = (const int*)d_in[1];
    const float* W1   = (const float*)d_in[2];
    const float* b1   = (const float*)d_in[3];
    const float* Wmu  = (const float*)d_in[4];
    const float* bmu  = (const float*)d_in[5];
    const float* Wsig = (const float*)d_in[6];
    const float* bsig = (const float*)d_in[7];
    const float* gn   = (const float*)d_in[8];
    float* out = (float*)d_out;
    (void)in_sizes; (void)n_in; (void)out_size;

    static cudaStream_t s2 = []() {
        cudaStream_t s; cudaStreamCreateWithFlags(&s, cudaStreamNonBlocking); return s;
    }();
    static cudaEvent_t evF = []() {
        cudaEvent_t e; cudaEventCreateWithFlags(&e, cudaEventDisableTiming); return e;
    }();
    static cudaEvent_t evJ = []() {
        cudaEvent_t e; cudaEventCreateWithFlags(&e, cudaEventDisableTiming); return e;
    }();

    int smem_g1 = 4 * 128 * TPW * 4;       // 139264 (Ahi,Alo,Bhi,Blo)
    int smem_g2 = (64 + 128) * TPW * 4;    // 52224
    int smem_zz = 2 * STAGE_W * 4;         // 106496
    cudaFuncSetAttribute(k_gemm1_f, cudaFuncAttributeMaxDynamicSharedMemorySize, smem_g1);
    cudaFuncSetAttribute(k_gemm2, cudaFuncAttributeMaxDynamicSharedMemorySize, smem_g2);
    cudaFuncSetAttribute(k_zzt_sym, cudaFuncAttributeMaxDynamicSharedMemorySize, smem_zz);

    // fork: side stream runs the CSR build chain
    cudaEventRecord(evF, 0);
    cudaStreamWaitEvent(s2, evF, 0);
    k_zero_cnt<<<Nn / 256, 256, 0, s2>>>();
    k_deg_i<<<EE / 256, 256, 0, s2>>>(ei);
    k_scan<<<1, 256, 0, s2>>>();
    k_fill<<<EE / 256, 256, 0, s2>>>(ei);
    cudaEventRecord(evJ, s2);

    // main stream: splits + layer-1 GEMM (independent of CSR build)
    k_split_x<<<(Nn * FIN / 4 + 255) / 256, 256>>>(x);
    k_split_w<<<(FIN * HH + HH * 128 + 255) / 256, 256>>>(W1, Wmu, Wsig);
    k_gemm1_f<<<dim3(2, 64), 256, smem_g1>>>();

    // join: gather needs CSR + dinv + gemm1 output
    cudaStreamWaitEvent(0, evJ, 0);
    k_gather1<<<Nn, 64>>>(b1);

    // layer 2
    k_gemm2<<<dim3(1, 128), 256, smem_g2>>>();
    k_gather2<<<Nn, 32>>>(gn, bmu, bsig);

    k_zzt_sym<<<NTRI, 256, smem_zz>>>(out);
}